// round 2
// baseline (speedup 1.0000x reference)
#include <cuda_runtime.h>
#include <cstdint>

// ---------------------------------------------------------------------------
// GAT_73572789781154 — fused GAT (2 layers) for B=1, N=4096, 8 heads, nhid=16
// Strategy:
//   K1: pack adj -> bitmask (2MB)            (removes 576MB of adj traffic)
//   K2: Wh = x @ W per head                  (tiny)
//   K3: s' = (Wh·a_src)·log2e, d' likewise   (tiny)
//   K4: per-head stability constant C_h      (tiny)
//   K5: layer-1 attention: per (i,j) pair -> ex2(lrelu) weight, masked by bit,
//       16-wide accumulate; ELU; write concat layout x2[n][h*16+o]
//   K6: Wh2 = x2 @ W_out, src2/dst2          (tiny)
//   K7: stability constant C2                (tiny)
//   K8: layer-2 attention (scalar channel) -> ELU -> d_out
// ---------------------------------------------------------------------------

#define N_NODES 4096
#define NHEADS  8
#define NHID    16
#define NFEAT   6
#define WORDS_PER_ROW (N_NODES / 32)   // 128
#define LOG2E 1.4426950408889634f

// scratch (device globals — no allocation allowed)
__device__ __align__(16) unsigned g_adjbits[N_NODES * WORDS_PER_ROW];   // 2 MB
__device__ __align__(16) float    g_Wh[NHEADS * N_NODES * NHID];        // 2 MB
__device__ __align__(16) float    g_sP[NHEADS * N_NODES];
__device__ __align__(16) float    g_dP[NHEADS * N_NODES];
__device__              float     g_C1[NHEADS];
__device__ __align__(16) float    g_x2[N_NODES * NHEADS * NHID];        // 2 MB
__device__ __align__(16) float    g_Wh2[N_NODES];
__device__ __align__(16) float    g_src2[N_NODES];
__device__ __align__(16) float    g_dst2[N_NODES];
__device__              float     g_C2;

__device__ __forceinline__ float ex2f(float x) {
    float r;
    asm("ex2.approx.ftz.f32 %0, %1;" : "=f"(r) : "f"(x));
    return r;
}

// ---------------- K1: pack adjacency into bitmask ----------------
__global__ void k_pack_adj(const int* __restrict__ adj) {
    int row = blockIdx.y;
    int j   = blockIdx.x * 256 + threadIdx.x;
    int v = adj[(size_t)row * N_NODES + j];
    unsigned word = __ballot_sync(0xFFFFFFFFu, v > 0);
    if ((threadIdx.x & 31) == 0)
        g_adjbits[row * WORDS_PER_ROW + (j >> 5)] = word;
}

// ---------------- K2: Wh[h][n][o] = sum_f x[n][f] * W[h][f][o] ----------------
__global__ void k_compute_wh(const float* __restrict__ x,   // (4096, 6)
                             const float* __restrict__ W) { // (8, 6, 16)
    int n = blockIdx.x;
    int t = threadIdx.x;            // 128 threads: (h, o)
    int h = t >> 4, o = t & 15;
    __shared__ float xs[NFEAT];
    if (t < NFEAT) xs[t] = x[n * NFEAT + t];
    __syncthreads();
    float acc = 0.f;
#pragma unroll
    for (int f = 0; f < NFEAT; ++f)
        acc += xs[f] * W[(h * NFEAT + f) * NHID + o];
    g_Wh[(h * N_NODES + n) * NHID + o] = acc;
}

// ---------------- K3: s' and d' (log2 domain) ----------------
__global__ void k_compute_sd(const float* __restrict__ a) { // (8, 32)
    int idx = blockIdx.x * blockDim.x + threadIdx.x;        // 32768
    int h = idx >> 12, n = idx & (N_NODES - 1);
    const float* wh = g_Wh + (h * N_NODES + n) * NHID;
    const float* ah = a + h * 2 * NHID;
    float s = 0.f, d = 0.f;
#pragma unroll
    for (int o = 0; o < NHID; ++o) {
        float v = wh[o];
        s += v * ah[o];
        d += v * ah[NHID + o];
    }
    g_sP[h * N_NODES + n] = s * LOG2E;
    g_dP[h * N_NODES + n] = d * LOG2E;
}

// ---------------- K4: C_h = max(s') + max(d') per head ----------------
__global__ void k_reduce_c1() {
    int h = blockIdx.x;
    int tid = threadIdx.x;
    float ms = -3.0e38f, md = -3.0e38f;
    for (int n = tid; n < N_NODES; n += 256) {
        ms = fmaxf(ms, g_sP[h * N_NODES + n]);
        md = fmaxf(md, g_dP[h * N_NODES + n]);
    }
    __shared__ float ss[256], sd[256];
    ss[tid] = ms; sd[tid] = md;
    __syncthreads();
    for (int s = 128; s > 0; s >>= 1) {
        if (tid < s) {
            ss[tid] = fmaxf(ss[tid], ss[tid + s]);
            sd[tid] = fmaxf(sd[tid], sd[tid + s]);
        }
        __syncthreads();
    }
    if (tid == 0) g_C1[h] = ss[0] + sd[0];
}

// ---------------- K5: layer-1 attention (the hot kernel) ----------------
#define TILE_I 128
#define TILE_J 128
__global__ __launch_bounds__(TILE_I) void k_layer1_attn() {
    int h = blockIdx.y;
    int i = blockIdx.x * TILE_I + threadIdx.x;

    __shared__ float4 sWh4[TILE_J * 4];   // 128 rows x 16 floats
    __shared__ float  sD[TILE_J];

    float sp   = g_sP[h * N_NODES + i];
    float Csub = g_C1[h];

    float acc[NHID];
#pragma unroll
    for (int o = 0; o < NHID; ++o) acc[o] = 0.f;
    float sum = 0.f;

    const float*    whHead  = g_Wh + (size_t)h * N_NODES * NHID;
    const float*    dHead   = g_dP + h * N_NODES;
    const unsigned* bitsRow = g_adjbits + (size_t)i * WORDS_PER_ROW;

    for (int jt = 0; jt < N_NODES / TILE_J; ++jt) {
        __syncthreads();   // protect previous tile's smem reads
        const float4* src = reinterpret_cast<const float4*>(whHead + (size_t)jt * TILE_J * NHID);
#pragma unroll
        for (int k = threadIdx.x; k < TILE_J * 4; k += TILE_I)
            sWh4[k] = src[k];
        if (threadIdx.x < TILE_J)
            sD[threadIdx.x] = dHead[jt * TILE_J + threadIdx.x];
        __syncthreads();

        uint4 mw = *reinterpret_cast<const uint4*>(bitsRow + jt * 4);
        unsigned wordArr[4] = {mw.x, mw.y, mw.z, mw.w};

#pragma unroll
        for (int w = 0; w < 4; ++w) {
            unsigned word = wordArr[w];
#pragma unroll 8
            for (int b = 0; b < 32; ++b) {
                int j = w * 32 + b;
                float v = sp + sD[j];
                float e = fmaxf(v, 0.2f * v) - Csub;      // lrelu in log2 domain
                e = (word & (1u << b)) ? e : -1.0e30f;    // masked -> ex2 gives 0
                float wt = ex2f(e);
                sum += wt;
                float4 p0 = sWh4[j * 4 + 0];
                float4 p1 = sWh4[j * 4 + 1];
                float4 p2 = sWh4[j * 4 + 2];
                float4 p3 = sWh4[j * 4 + 3];
                acc[0]  += wt * p0.x;  acc[1]  += wt * p0.y;
                acc[2]  += wt * p0.z;  acc[3]  += wt * p0.w;
                acc[4]  += wt * p1.x;  acc[5]  += wt * p1.y;
                acc[6]  += wt * p1.z;  acc[7]  += wt * p1.w;
                acc[8]  += wt * p2.x;  acc[9]  += wt * p2.y;
                acc[10] += wt * p2.z;  acc[11] += wt * p2.w;
                acc[12] += wt * p3.x;  acc[13] += wt * p3.y;
                acc[14] += wt * p3.z;  acc[15] += wt * p3.w;
            }
        }
    }

    float rn = 1.0f / sum;
    float* out = g_x2 + (size_t)i * (NHEADS * NHID) + h * NHID;
#pragma unroll
    for (int o = 0; o < NHID; ++o) {
        float vv = acc[o] * rn;
        out[o] = (vv > 0.f) ? vv : (expf(vv) - 1.0f);     // ELU
    }
}

// ---------------- K6: Wh2 = x2 @ W_out (C=1), src2/dst2 ----------------
__global__ void k_compute_wh2(const float* __restrict__ Wout,   // (128,)
                              const float* __restrict__ aout) { // (2,)
    int warp = threadIdx.x >> 5, lane = threadIdx.x & 31;
    int n = blockIdx.x * 4 + warp;
    const float* row = g_x2 + (size_t)n * (NHEADS * NHID);
    float s = 0.f;
#pragma unroll
    for (int k = 0; k < 4; ++k)
        s += row[lane + 32 * k] * Wout[lane + 32 * k];
#pragma unroll
    for (int off = 16; off > 0; off >>= 1)
        s += __shfl_xor_sync(0xFFFFFFFFu, s, off);
    if (lane == 0) {
        g_Wh2[n]  = s;
        g_src2[n] = s * aout[0] * LOG2E;
        g_dst2[n] = s * aout[1] * LOG2E;
    }
}

// ---------------- K7: C2 = max(src2) + max(dst2) ----------------
__global__ void k_reduce_c2() {
    int tid = threadIdx.x;
    float ms = -3.0e38f, md = -3.0e38f;
    for (int n = tid; n < N_NODES; n += 256) {
        ms = fmaxf(ms, g_src2[n]);
        md = fmaxf(md, g_dst2[n]);
    }
    __shared__ float ss[256], sd[256];
    ss[tid] = ms; sd[tid] = md;
    __syncthreads();
    for (int s = 128; s > 0; s >>= 1) {
        if (tid < s) {
            ss[tid] = fmaxf(ss[tid], ss[tid + s]);
            sd[tid] = fmaxf(sd[tid], sd[tid + s]);
        }
        __syncthreads();
    }
    if (tid == 0) g_C2 = ss[0] + sd[0];
}

// ---------------- K8: layer-2 attention -> output ----------------
__global__ __launch_bounds__(256) void k_layer2_attn(float* __restrict__ out) {
    int warp = threadIdx.x >> 5, lane = threadIdx.x & 31;
    int i = blockIdx.x * 8 + warp;
    float sp   = g_src2[i];
    float Csub = g_C2;
    const unsigned* bitsRow = g_adjbits + (size_t)i * WORDS_PER_ROW;
    float sum = 0.f, acc = 0.f;
#pragma unroll 4
    for (int k = 0; k < WORDS_PER_ROW; ++k) {
        unsigned word = __ldg(bitsRow + k);   // broadcast across warp
        int j = k * 32 + lane;
        float v = sp + g_dst2[j];
        float e = fmaxf(v, 0.2f * v) - Csub;
        e = (word & (1u << lane)) ? e : -1.0e30f;
        float wt = ex2f(e);
        sum += wt;
        acc += wt * g_Wh2[j];
    }
#pragma unroll
    for (int off = 16; off > 0; off >>= 1) {
        sum += __shfl_xor_sync(0xFFFFFFFFu, sum, off);
        acc += __shfl_xor_sync(0xFFFFFFFFu, acc, off);
    }
    if (lane == 0) {
        float vv = acc / sum;
        out[i] = (vv > 0.f) ? vv : (expf(vv) - 1.0f);
    }
}

// ---------------------------------------------------------------------------
extern "C" void kernel_launch(void* const* d_in, const int* in_sizes, int n_in,
                              void* d_out, int out_size) {
    const float* flow_x = (const float*)d_in[0];   // (1,4096,6,1) -> (4096,6)
    const int*   adj    = (const int*)  d_in[1];   // (4096,4096)
    const float* W      = (const float*)d_in[2];   // (8,6,16)
    const float* a      = (const float*)d_in[3];   // (8,32)
    const float* W_out  = (const float*)d_in[4];   // (128,1)
    const float* a_out  = (const float*)d_in[5];   // (2,)
    float* out = (float*)d_out;                    // (4096,)

    (void)in_sizes; (void)n_in; (void)out_size;

    // K1: adjacency bitmask
    dim3 gPack(N_NODES / 256, N_NODES);
    k_pack_adj<<<gPack, 256>>>(adj);

    // K2: Wh
    k_compute_wh<<<N_NODES, NHEADS * NHID>>>(flow_x, W);

    // K3: s', d'
    k_compute_sd<<<(NHEADS * N_NODES) / 256, 256>>>(a);

    // K4: per-head stability constants
    k_reduce_c1<<<NHEADS, 256>>>();

    // K5: layer-1 attention (hot)
    dim3 gAttn(N_NODES / TILE_I, NHEADS);
    k_layer1_attn<<<gAttn, TILE_I>>>();

    // K6: Wh2 / src2 / dst2
    k_compute_wh2<<<N_NODES / 4, 128>>>(W_out, a_out);

    // K7: layer-2 stability constant
    k_reduce_c2<<<1, 256>>>();

    // K8: layer-2 attention -> d_out
    k_layer2_attn<<<N_NODES / 8, 256>>>(out);
}